// round 6
// baseline (speedup 1.0000x reference)
#include <cuda_runtime.h>
#include <math.h>

#define NP   31752
#define D_   192
#define NA   256
#define LMB  0.1f
#define NSQ  11
#define T_   72
#define NTHR 576
#define NCTA 441

typedef unsigned long long ull;

// ---------------- static device scratch ----------------
__device__ float g_A[NA * D_];     // normalized dictionary [a][d]
__device__ float g_At[D_ * NA];    // transposed [d][a]
__device__ float g_X[NA * NA];
__device__ float g_Ma[NA * NA];
__device__ float g_Mb[NA * NA];
__device__ float g_fs[16];         // sum-of-squares (Frobenius^2) per stage
__device__ float g_params[4];      // L, 1/L, lambda/L
__device__ float g_mean[NP];
__device__ float g_pt[D_ * NP];    // centered patches [d][n]
__device__ float g_rec[NP * D_];   // reconstruction [n][d]

__device__ __forceinline__ const float* pick(int id) {
    return id == 0 ? g_A : id == 1 ? g_X : id == 2 ? g_Ma : g_Mb;
}

// ---------------- f32x2 helpers ----------------
__device__ __forceinline__ ull pk2(float a, float b) {
    ull r; asm("mov.b64 %0, {%1,%2};" : "=l"(r) : "f"(a), "f"(b)); return r;
}
__device__ __forceinline__ ull f2fma(ull a, ull b, ull c) {
    ull d; asm("fma.rn.f32x2 %0, %1, %2, %3;" : "=l"(d) : "l"(a), "l"(b), "l"(c)); return d;
}
__device__ __forceinline__ void up2(ull v, float& lo, float& hi) {
    asm("mov.b64 {%0,%1}, %2;" : "=f"(lo), "=f"(hi) : "l"(v));
}

// ---------------- 1. normalize atoms (+ zero g_fs) ----------------
__global__ void k_norm(const float* __restrict__ atoms) {
    __shared__ float red[256];
    int r = blockIdx.x, t = threadIdx.x;
    if (r == 0 && t < 16) g_fs[t] = 0.f;
    float v = (t < D_) ? atoms[r * D_ + t] : 0.f;
    red[t] = v * v;
    __syncthreads();
    for (int o = 128; o > 0; o >>= 1) { if (t < o) red[t] += red[t + o]; __syncthreads(); }
    float inv = 1.0f / sqrtf(red[0]);
    if (t < D_) { float a = v * inv; g_A[r * D_ + t] = a; g_At[t * NA + r] = a; }
}

// ---------------- 2. Out = scale * In In^T, fused Frobenius^2 of Out ----------------
__global__ void k_mmT(int inId, int outId, int K, int fin, int fout) {
    __shared__ float As[16][17], Bs[16][17];
    const float* In = pick(inId);
    float* Out = (float*)pick(outId);
    int tx = threadIdx.x, ty = threadIdx.y;
    int row = blockIdx.y * 16 + ty, col0 = blockIdx.x * 16;
    float scale = (fin >= 0) ? 1.0f / g_fs[fin] : 1.0f;
    float a_pf = In[row * K + tx];
    float b_pf = In[(col0 + ty) * K + tx];
    float acc = 0.f;
    for (int kt = 0; kt < K; kt += 16) {
        As[ty][tx] = a_pf; Bs[ty][tx] = b_pf;
        __syncthreads();
        if (kt + 16 < K) {
            a_pf = In[row * K + kt + 16 + tx];
            b_pf = In[(col0 + ty) * K + kt + 16 + tx];
        }
        float s = 0.f;
#pragma unroll
        for (int kk = 0; kk < 16; kk++) s += As[ty][kk] * Bs[tx][kk];
        acc += s;
        __syncthreads();
    }
    float o = acc * scale;
    Out[row * NA + col0 + tx] = o;
    if (fout >= 0) {
        float fsum = o * o;
#pragma unroll
        for (int off = 16; off > 0; off >>= 1) fsum += __shfl_xor_sync(0xffffffffu, fsum, off);
        if (((ty * 16 + tx) & 31) == 0) atomicAdd(&g_fs[fout], fsum);
    }
}

// ---------------- 3. spectral norm assembly ----------------
__global__ void k_param(int srcId) {
    __shared__ float red[256];
    const float* M = pick(srcId);
    int t = threadIdx.x;
    red[t] = M[t * NA + t];
    __syncthreads();
    for (int o = 128; o > 0; o >>= 1) { if (t < o) red[t] += red[t + o]; __syncthreads(); }
    if (t == 0) {
        double lg = log((double)red[0]);
        for (int j = 1; j <= NSQ; j++)
            lg += (double)(1 << (NSQ - j)) * log((double)g_fs[j]);
        double L = exp(lg / (double)(1 << NSQ));
        g_params[0] = (float)L;
        g_params[1] = (float)(1.0 / L);
        g_params[2] = (float)((double)LMB / L);
    }
}

// ---------------- 4. per-patch mean ----------------
__global__ void k_mean(const float* __restrict__ y) {
    int n = blockIdx.x * 8 + (threadIdx.x >> 5);
    int l = threadIdx.x & 31;
    int b = n / 3969, r = n % 3969, i = r / 63, j = r % 63;
    float s = 0.f;
    for (int d = l; d < D_; d += 32) {
        int ch = d >> 6, u = (d >> 3) & 7, v = d & 7;
        s += y[((b * 3 + ch) * 256 + i * 4 + u) * 256 + j * 4 + v];
    }
    for (int o = 16; o > 0; o >>= 1) s += __shfl_xor_sync(0xffffffffu, s, o);
    if (l == 0) g_mean[n] = s * (1.f / 192.f);
}

// ---------------- 5. centered patches, d-major ----------------
__global__ void k_pt(const float* __restrict__ y) {
    int n = blockIdx.x * 256 + threadIdx.x;
    if (n >= NP) return;
    int d = blockIdx.y;
    int b = n / 3969, r = n % 3969, i = r / 63, j = r % 63;
    int ch = d >> 6, u = (d >> 3) & 7, v = d & 7;
    g_pt[d * NP + n] = y[((b * 3 + ch) * 256 + i * 4 + u) * 256 + j * 4 + v] - g_mean[n];
}

// ---------------- fused q + ISTA + rec ----------------
// SMEM floats: cs[256*T_] | qs[256*T_] | Xdup (2*16*256 ull = 16384 floats) | msh[T_]
#define CS_OFF 0
#define QS_OFF (256 * T_)
#define XD_OFF (2 * 256 * T_)
#define MS_OFF (XD_OFF + 16384)
#define SM_FLOATS (MS_OFF + T_)

// acc[RPT rows][2 col-pairs] += M(slab-streamed, duplicated) @ csrc
// gsrc: nslab slabs of [16][ROWLEN] floats (contiguous); csrc: [16*nslab][T_]
template <int RPT, int ROWLEN>
__device__ __forceinline__ void slab_gemm(ull (&acc)[RPT][2], const float* __restrict__ gsrc,
                                          const float* csrc, ull* Xd,
                                          int nslab, int r0, int j0, int tid) {
    constexpr int CNT = 16 * ROWLEN;
    constexpr int NPF = (CNT + NTHR - 1) / NTHR;
    // preload slab 0 (duplicated)
#pragma unroll
    for (int t = 0; t < NPF; t++) {
        int i = tid + t * NTHR;
        if (i < CNT) { float v = gsrc[i]; Xd[i] = pk2(v, v); }
    }
    __syncthreads();
    for (int s = 0; s < nslab; s++) {
        float pf[NPF];
        if (s + 1 < nslab) {
            const float* src = gsrc + (s + 1) * CNT;
#pragma unroll
            for (int t = 0; t < NPF; t++) {
                int i = tid + t * NTHR;
                if (i < CNT) pf[t] = src[i];
            }
        }
        const ull* Xb = Xd + (s & 1) * CNT;
        const float* cb = csrc + s * 16 * T_;
#pragma unroll
        for (int kk = 0; kk < 16; kk++) {
            const ull* Xr = Xb + kk * ROWLEN + r0;
            ulonglong2 cp = *(const ulonglong2*)&cb[kk * T_ + j0];
#pragma unroll
            for (int rp = 0; rp < RPT / 2; rp++) {
                ulonglong2 xp = *(const ulonglong2*)(Xr + 2 * rp);
                acc[2 * rp][0]     = f2fma(xp.x, cp.x, acc[2 * rp][0]);
                acc[2 * rp][1]     = f2fma(xp.x, cp.y, acc[2 * rp][1]);
                acc[2 * rp + 1][0] = f2fma(xp.y, cp.x, acc[2 * rp + 1][0]);
                acc[2 * rp + 1][1] = f2fma(xp.y, cp.y, acc[2 * rp + 1][1]);
            }
        }
        __syncthreads();
        if (s + 1 < nslab) {
            ull* dst = Xd + ((s + 1) & 1) * CNT;
#pragma unroll
            for (int t = 0; t < NPF; t++) {
                int i = tid + t * NTHR;
                if (i < CNT) dst[i] = pk2(pf[t], pf[t]);
            }
            __syncthreads();
        }
    }
}

__device__ __forceinline__ float softthr(float v, float thr) {
    float a = fabsf(v) - thr;
    return a > 0.f ? copysignf(a, v) : 0.f;
}

__global__ void __launch_bounds__(NTHR, 1) k_fused() {
    extern __shared__ float sm[];
    float* cs = sm + CS_OFF;
    float* qs = sm + QS_OFF;
    ull* Xd = (ull*)(sm + XD_OFF);
    float* msh = sm + MS_OFF;
    const int tid = threadIdx.x;
    const int n0 = blockIdx.x * T_;
    const int cg = tid % 18, rg = tid / 18;
    const int j0 = cg * 4, r0 = rg * 8;
    const float invL = g_params[1], thr = g_params[2];

    // load centered patch tile (d-major) + mean tile
    for (int i = tid; i < D_ * T_; i += NTHR)
        cs[i] = g_pt[(i / T_) * NP + n0 + (i % T_)];
    if (tid < T_) msh[tid] = g_mean[n0 + tid];
    // slab_gemm's first internal barrier orders these writes before any read

    ull acc[8][2];
#pragma unroll
    for (int a = 0; a < 8; a++) { acc[a][0] = 0ull; acc[a][1] = 0ull; }

    // ---- prologue: q = A @ p^T  (contraction over d: gsrc = At[d][a]) ----
    slab_gemm<8, 256>(acc, g_At, cs, Xd, 12, r0, j0, tid);

    // store q to smem; first ISTA step c = soft(q/L) into registers
    ull c[8][2];
#pragma unroll
    for (int rp = 0; rp < 8; rp++) {
        ulonglong2 qv; qv.x = acc[rp][0]; qv.y = acc[rp][1];
        *(ulonglong2*)&qs[(r0 + rp) * T_ + j0] = qv;
#pragma unroll
        for (int jp = 0; jp < 2; jp++) {
            float lo, hi; up2(acc[rp][jp], lo, hi);
            c[rp][jp] = pk2(softthr(lo * invL, thr), softthr(hi * invL, thr));
        }
        ulonglong2 cv; cv.x = c[rp][0]; cv.y = c[rp][1];
        *(ulonglong2*)&cs[(r0 + rp) * T_ + j0] = cv;
    }
    // next gemm's preload barrier orders cs/qs writes before reads

    // ---- 24 remaining ISTA iterations ----
    for (int it = 0; it < 24; it++) {
#pragma unroll
        for (int a = 0; a < 8; a++) { acc[a][0] = 0ull; acc[a][1] = 0ull; }
        slab_gemm<8, 256>(acc, g_X, cs, Xd, 16, r0, j0, tid);
#pragma unroll
        for (int rp = 0; rp < 8; rp++) {
#pragma unroll
            for (int jp = 0; jp < 2; jp++) {
                float alo, ahi; up2(acc[rp][jp], alo, ahi);
                float clo, chi; up2(c[rp][jp], clo, chi);
                float qlo = qs[(r0 + rp) * T_ + j0 + 2 * jp];
                float qhi = qs[(r0 + rp) * T_ + j0 + 2 * jp + 1];
                float vlo = clo - (alo - qlo) * invL;
                float vhi = chi - (ahi - qhi) * invL;
                c[rp][jp] = pk2(softthr(vlo, thr), softthr(vhi, thr));
            }
            ulonglong2 cv; cv.x = c[rp][0]; cv.y = c[rp][1];
            *(ulonglong2*)&cs[(r0 + rp) * T_ + j0] = cv;
        }
    }

    // ---- epilogue: rec = c^T A + mean (contraction over atoms: gsrc = A[a][d]) ----
    {
        const int r0e = rg * 6;  // 32 groups x 6 rows = 192 d-rows
        ull racc[6][2];
#pragma unroll
        for (int a = 0; a < 6; a++) { racc[a][0] = 0ull; racc[a][1] = 0ull; }
        slab_gemm<6, 192>(racc, g_A, cs, Xd, 16, r0e, j0, tid);
#pragma unroll
        for (int rp = 0; rp < 6; rp++) {
#pragma unroll
            for (int jp = 0; jp < 2; jp++) {
                float lo, hi; up2(racc[rp][jp], lo, hi);
                int na = n0 + j0 + 2 * jp;
                g_rec[(size_t)na * D_ + r0e + rp]       = lo + msh[j0 + 2 * jp];
                g_rec[(size_t)(na + 1) * D_ + r0e + rp] = hi + msh[j0 + 2 * jp + 1];
            }
        }
    }
}

// ---------------- overlap-add + count division ----------------
__global__ void k_out(float* __restrict__ out) {
    int idx = blockIdx.x * 256 + threadIdx.x;
    if (idx >= 8 * 3 * 256 * 256) return;
    int w = idx & 255, h = (idx >> 8) & 255;
    int ch = (idx >> 16) % 3, b = (idx >> 16) / 3;
    int ihi = h >> 2; if (ihi > 62) ihi = 62;
    int ilo = (h >= 7) ? ((h - 4) >> 2) : 0;
    int jhi = w >> 2; if (jhi > 62) jhi = 62;
    int jlo = (w >= 7) ? ((w - 4) >> 2) : 0;
    float s = 0.f;
    int cnt = 0;
    for (int i = ilo; i <= ihi; i++) {
        int u = h - 4 * i;
        for (int j = jlo; j <= jhi; j++) {
            int v = w - 4 * j;
            int n = b * 3969 + i * 63 + j;
            s += g_rec[(size_t)n * D_ + ch * 64 + u * 8 + v];
            cnt++;
        }
    }
    out[idx] = s / (float)cnt;
}

// ---------------- host launcher ----------------
extern "C" void kernel_launch(void* const* d_in, const int* in_sizes, int n_in,
                              void* d_out, int out_size) {
    const float* y = (const float*)d_in[0];
    const float* atoms = (const float*)d_in[1];
    if (n_in >= 2 && in_sizes[0] < in_sizes[1]) {
        y = (const float*)d_in[1];
        atoms = (const float*)d_in[0];
    }
    float* out = (float*)d_out;

    k_norm<<<NA, 256>>>(atoms);
    k_mmT<<<dim3(16, 16), dim3(16, 16)>>>(0, 1, D_, -1, 1);  // X = A A^T, fs[1]
    int src = 1;
    for (int j = 1; j <= NSQ; j++) {
        int dst = (j & 1) ? 2 : 3;
        k_mmT<<<dim3(16, 16), dim3(16, 16)>>>(src, dst, NA, j, j + 1);
        src = dst;
    }
    k_param<<<1, 256>>>(src);
    k_mean<<<NP / 8, 256>>>(y);
    k_pt<<<dim3(125, D_), 256>>>(y);

    cudaFuncSetAttribute(k_fused, cudaFuncAttributeMaxDynamicSharedMemorySize,
                         SM_FLOATS * (int)sizeof(float));
    k_fused<<<NCTA, NTHR, SM_FLOATS * sizeof(float)>>>();

    k_out<<<(8 * 3 * 256 * 256 + 255) / 256, 256>>>(out);
}